// round 7
// baseline (speedup 1.0000x reference)
#include <cuda_runtime.h>
#include <math.h>

// Fixed problem shapes
#define B_    4
#define N_    10
#define K_    5
#define Q_    512
#define D_    1536
#define D4_   384            // float4 per row

#define NP_   64             // partial sums per batch (8 query rows each)
#define NBLK_ 128            // B * 32 phase-1 blocks, one co-resident wave
#define NT_   768            // 2 halves x 384 columns
#define NW_   24
#define NP2_  (B_ * N_)      // 40 phase-2 blocks
#define GWT_  (B_ * D4_)     // 1536 = total (batch,col) reduce warps

// Scratch (allocation-free device globals)
__device__ float4   g_qsumT[B_ * D4_ * NP_];  // [(b*D4+col)*NP + p] transposed partials
__device__ float    g_ss[NBLK_];              // per-block sum of squares
__device__ float4   g_qbar4[B_ * D4_];        // reduced mean query vectors
__device__ float    g_c[B_];                  // mean ||q||^2 per batch
__device__ unsigned g_cntA, g_cntB;           // monotone wrap-safe barrier counters

__global__ void __launch_bounds__(NT_, 1)
fused_kernel(const float4* __restrict__ q4,
             const float4* __restrict__ sup4,
             float* __restrict__ out) {
    const int tid  = threadIdx.x;
    const int lane = tid & 31;
    const int wid  = tid >> 5;
    const int bid  = blockIdx.x;
    const int col  = (tid < D4_) ? tid : tid - D4_;   // 0..383
    const int half = (tid >= D4_) ? 1 : 0;

    __shared__ float4 s_sv[K_ * D4_];     // prefetched support tile (30 KB)
    __shared__ float  s_wred[NW_];
    __shared__ float  s_red[2 * K_ * 12];
    __shared__ float  s_w[K_];

    const bool is_p2 = (bid < NP2_);

    // ---- phase-2 support prefetch: issue DRAM loads at the very top ----
    float4 sv0, sv1, sv2, sv3, sv4;
    if (is_p2 && tid < D4_) {
        const float4* sp = sup4 + (size_t)bid * K_ * D4_ + col;
        sv0 = sp[0];        sv1 = sp[D4_];     sv2 = sp[2 * D4_];
        sv3 = sp[3 * D4_];  sv4 = sp[4 * D4_];
    }

    // ======================= Phase 1: query stats =======================
    const int b  = bid >> 5;
    const int qs = bid & 31;
    {
        // this thread's 8 rows: qs*16 + half + 2*i
        const float4* qp = q4 + ((size_t)(b * Q_ + qs * 16 + half)) * D4_ + col;

        float4 s = make_float4(0.f, 0.f, 0.f, 0.f);
        float ss = 0.f;
        #pragma unroll
        for (int i = 0; i < 8; i++) {
            float4 v = qp[(size_t)(2 * i) * D4_];
            s.x += v.x; s.y += v.y; s.z += v.z; s.w += v.w;
            ss += v.x * v.x + v.y * v.y + v.z * v.z + v.w * v.w;
        }
        // transposed partial write: no cross-half combine needed
        g_qsumT[((size_t)(b * D4_ + col)) * NP_ + qs * 2 + half] = s;

        #pragma unroll
        for (int off = 16; off > 0; off >>= 1)
            ss += __shfl_down_sync(0xffffffffu, ss, off);
        if (lane == 0) s_wred[wid] = ss;

        // stash prefetched support into shared (loads have landed by now)
        if (is_p2 && tid < D4_) {
            s_sv[0 * D4_ + col] = sv0; s_sv[1 * D4_ + col] = sv1;
            s_sv[2 * D4_ + col] = sv2; s_sv[3 * D4_ + col] = sv3;
            s_sv[4 * D4_ + col] = sv4;
        }
        __syncthreads();
        if (tid == 0) {
            float t = 0.f;
            #pragma unroll
            for (int w = 0; w < NW_; w++) t += s_wred[w];
            g_ss[bid] = t;
        }
    }

    // ======================= Barrier A (all blocks wait) =======================
    __threadfence();
    __syncthreads();
    if (tid == 0) {
        unsigned old = atomicAdd(&g_cntA, 1u);
        unsigned target = old - (old & (NBLK_ - 1)) + NBLK_;   // wrap-safe
        while ((int)(*(volatile unsigned*)&g_cntA - target) < 0) { }
        __threadfence();
    }
    __syncthreads();

    // ============== Phase 1.5: distributed qbar reduction =====================
    // 128 blocks x 12 warps = 1536 warps == one warp per (batch, col).
    if (wid < 12) {
        const int gw = bid * 12 + wid;            // 0..1535 = bb*384 + col
        const float4* p = g_qsumT + (size_t)gw * NP_ + lane * 2;
        float4 a = p[0], b2 = p[1];               // coalesced 1KB per warp
        a.x += b2.x; a.y += b2.y; a.z += b2.z; a.w += b2.w;
        #pragma unroll
        for (int off = 16; off > 0; off >>= 1) {
            a.x += __shfl_down_sync(0xffffffffu, a.x, off);
            a.y += __shfl_down_sync(0xffffffffu, a.y, off);
            a.z += __shfl_down_sync(0xffffffffu, a.z, off);
            a.w += __shfl_down_sync(0xffffffffu, a.w, off);
        }
        if (lane == 0) {
            const float invQ = 1.0f / Q_;
            a.x *= invQ; a.y *= invQ; a.z *= invQ; a.w *= invQ;
            g_qbar4[gw] = a;
        }
    } else if (wid == 12 && bid < B_) {
        float cv = g_ss[bid * 32 + lane];
        #pragma unroll
        for (int off = 16; off > 0; off >>= 1)
            cv += __shfl_down_sync(0xffffffffu, cv, off);
        if (lane == 0) g_c[bid] = cv * (1.0f / Q_);
    }

    // ======================= Barrier B (only phase-2 blocks wait) =============
    __threadfence();
    __syncthreads();
    if (tid == 0) {
        unsigned old = atomicAdd(&g_cntB, 1u);
        if (is_p2) {
            unsigned target = old - (old & (NBLK_ - 1)) + NBLK_;
            while ((int)(*(volatile unsigned*)&g_cntB - target) < 0) { }
            __threadfence();
        }
    }
    if (!is_p2) return;
    __syncthreads();

    // ======================= Phase 2: weights + aggregation ===================
    const int bn = bid;
    const int bb = bn / N_;

    if (tid < D4_) {
        float4 qb = g_qbar4[bb * D4_ + col];      // 6 KB coalesced, L2-hit
        float dot[K_], nrm[K_];
        #pragma unroll
        for (int k = 0; k < K_; k++) {
            float4 sv = s_sv[k * D4_ + col];
            dot[k] = sv.x * qb.x + sv.y * qb.y + sv.z * qb.z + sv.w * qb.w;
            nrm[k] = sv.x * sv.x + sv.y * sv.y + sv.z * sv.z + sv.w * sv.w;
        }
        #pragma unroll
        for (int k = 0; k < K_; k++) {
            float dk = dot[k], nk = nrm[k];
            #pragma unroll
            for (int off = 16; off > 0; off >>= 1) {
                dk += __shfl_down_sync(0xffffffffu, dk, off);
                nk += __shfl_down_sync(0xffffffffu, nk, off);
            }
            if (lane == 0) {
                s_red[k * 12 + wid]        = dk;
                s_red[(K_ + k) * 12 + wid] = nk;
            }
        }
    }
    __syncthreads();

    // softmax across 5 lanes of warp 0 (lanes 5..7 padded for the butterflies)
    if (wid == 0 && lane < 8) {
        const bool valid = (lane < K_);
        float c = g_c[bb];                         // broadcast L2 load
        float t = -1e30f;
        if (valid) {
            float dk = 0.f, nk = 0.f;
            #pragma unroll
            for (int w = 0; w < 12; w++) {
                dk += s_red[lane * 12 + w];
                nk += s_red[(K_ + lane) * 12 + w];
            }
            t = tanhf(-(nk - 2.0f * dk + c));
        }
        float m = t;
        #pragma unroll
        for (int off = 4; off > 0; off >>= 1)
            m = fmaxf(m, __shfl_xor_sync(0xffu, m, off, 8));
        float e = valid ? __expf(t - m) : 0.f;
        float Z = e;
        #pragma unroll
        for (int off = 4; off > 0; off >>= 1)
            Z += __shfl_xor_sync(0xffu, Z, off, 8);
        if (valid) {
            float wk = e / Z;
            s_w[lane] = wk;
            out[(size_t)B_ * N_ * D_ + bn * K_ + lane] = wk;   // qgw
        }
    }
    __syncthreads();

    if (tid < D4_) {
        float4 acc = make_float4(0.f, 0.f, 0.f, 0.f);
        #pragma unroll
        for (int k = 0; k < K_; k++) {
            float wk = s_w[k];
            float4 sv = s_sv[k * D4_ + col];
            acc.x += wk * sv.x; acc.y += wk * sv.y;
            acc.z += wk * sv.z; acc.w += wk * sv.w;
        }
        ((float4*)out)[(size_t)bn * D4_ + col] = acc;          // agg
    }
}

extern "C" void kernel_launch(void* const* d_in, const int* in_sizes, int n_in,
                              void* d_out, int out_size) {
    const float4* support = (const float4*)d_in[0];
    const float4* query   = (const float4*)d_in[1];
    float* out = (float*)d_out;

    fused_kernel<<<NBLK_, NT_>>>(query, support, out);
}

// round 12
// speedup vs baseline: 1.4468x; 1.4468x over previous
#include <cuda_runtime.h>
#include <math.h>

// Fixed problem shapes
#define B_    4
#define N_    10
#define K_    5
#define Q_    512
#define D_    1536
#define D4_   384            // float4 per row

#define SLC_  12             // float4 columns per slice
#define NSL_  32             // slices per batch (32*12 = 384)
#define NBLK_ 128            // B * NSL, one co-resident wave
#define NT_   768            // 64 row-groups x 12 columns
#define NW_   24
#define NP2_  (B_ * N_)      // 40 phase-2 blocks
#define PITCH_ 13            // padded float4 pitch (bank-conflict relief)

// Scratch (allocation-free device globals)
__device__ float4   g_qbar4[B_ * D4_];   // finished mean query vectors
__device__ float    g_ss[NBLK_];         // per-(b,slice) sum of squares
__device__ unsigned g_cnt;               // monotone wrap-safe barrier counter

__global__ void __launch_bounds__(NT_, 1)
fused_kernel(const float4* __restrict__ q4,
             const float4* __restrict__ sup4,
             float* __restrict__ out) {
    const int tid  = threadIdx.x;
    const int lane = tid & 31;
    const int wid  = tid >> 5;
    const int bid  = blockIdx.x;

    __shared__ float4 s_part[64 * PITCH_];   // per-(row-group, col) partials (13 KB)
    __shared__ float4 s_sv[K_ * D4_];        // prefetched support tile (30 KB)
    __shared__ float  s_wred[NW_];
    __shared__ float  s_red[2 * K_ * 12];
    __shared__ float  s_w[K_];
    __shared__ float  s_c;

    const bool is_p2 = (bid < NP2_);
    const int  col   = (tid < D4_) ? tid : tid - D4_;   // phase-2 column

    // ---- phase-2 support prefetch: issue DRAM loads at the very top ----
    float4 sv0, sv1, sv2, sv3, sv4;
    if (is_p2 && tid < D4_) {
        const float4* sp = sup4 + (size_t)bid * K_ * D4_ + col;
        sv0 = sp[0];        sv1 = sp[D4_];     sv2 = sp[2 * D4_];
        sv3 = sp[3 * D4_];  sv4 = sp[4 * D4_];
    }

    // ============ Phase 1: column-sliced query stats (no cross-block partials) ====
    const int b  = bid >> 5;          // batch
    const int sl = bid & 31;          // column slice
    {
        const int rg = tid / SLC_;            // row group 0..63
        const int c  = tid - rg * SLC_;       // column-in-slice 0..11
        const float4* qp = q4 + ((size_t)(b * Q_ + rg)) * D4_ + sl * SLC_ + c;

        float4 s = make_float4(0.f, 0.f, 0.f, 0.f);
        float ss = 0.f;
        #pragma unroll
        for (int i = 0; i < 8; i++) {         // rows rg + 64*i
            float4 v = qp[(size_t)(64 * i) * D4_];
            s.x += v.x; s.y += v.y; s.z += v.z; s.w += v.w;
            ss += v.x * v.x + v.y * v.y + v.z * v.z + v.w * v.w;
        }
        s_part[rg * PITCH_ + c] = s;

        #pragma unroll
        for (int off = 16; off > 0; off >>= 1)
            ss += __shfl_down_sync(0xffffffffu, ss, off);
        if (lane == 0) s_wred[wid] = ss;

        // stash prefetched support into shared (loads have landed by now)
        if (is_p2 && tid < D4_) {
            s_sv[0 * D4_ + col] = sv0; s_sv[1 * D4_ + col] = sv1;
            s_sv[2 * D4_ + col] = sv2; s_sv[3 * D4_ + col] = sv3;
            s_sv[4 * D4_ + col] = sv4;
        }
        __syncthreads();

        if (tid == 0) {
            float t = 0.f;
            #pragma unroll
            for (int w = 0; w < NW_; w++) t += s_wred[w];
            g_ss[bid] = t;
        }
        // one warp per column: fold 64 row-group partials -> final column sum
        if (wid < SLC_) {
            float4 a = s_part[lane * PITCH_ + wid];
            float4 b2 = s_part[(lane + 32) * PITCH_ + wid];
            a.x += b2.x; a.y += b2.y; a.z += b2.z; a.w += b2.w;
            #pragma unroll
            for (int off = 16; off > 0; off >>= 1) {
                a.x += __shfl_down_sync(0xffffffffu, a.x, off);
                a.y += __shfl_down_sync(0xffffffffu, a.y, off);
                a.z += __shfl_down_sync(0xffffffffu, a.z, off);
                a.w += __shfl_down_sync(0xffffffffu, a.w, off);
            }
            if (lane == 0) {
                const float invQ = 1.0f / Q_;
                a.x *= invQ; a.y *= invQ; a.z *= invQ; a.w *= invQ;
                g_qbar4[b * D4_ + sl * SLC_ + wid] = a;    // finished qbar
            }
        }
    }

    // ============ Barrier: all arrive, only phase-2 blocks spin ============
    __threadfence();
    __syncthreads();
    if (tid == 0) {
        unsigned old = atomicAdd(&g_cnt, 1u);
        if (is_p2) {
            unsigned target = old - (old & (NBLK_ - 1)) + NBLK_;   // wrap-safe
            while ((int)(*(volatile unsigned*)&g_cnt - target) < 0) { }
            __threadfence();
        }
    }
    if (!is_p2) return;
    __syncthreads();

    // ============ Phase 2: weights + aggregation (40 blocks) ============
    const int bn = bid;
    const int bb = bn / N_;

    // c_b = mean_q ||q||^2 (warp 1)
    if (wid == 1) {
        float cv = g_ss[bb * NSL_ + lane];
        #pragma unroll
        for (int off = 16; off > 0; off >>= 1)
            cv += __shfl_down_sync(0xffffffffu, cv, off);
        if (lane == 0) s_c = cv * (1.0f / Q_);
    }

    if (tid < D4_) {
        float4 qb = g_qbar4[bb * D4_ + col];      // 6 KB coalesced L2 read
        float dot[K_], nrm[K_];
        #pragma unroll
        for (int k = 0; k < K_; k++) {
            float4 sv = s_sv[k * D4_ + col];
            dot[k] = sv.x * qb.x + sv.y * qb.y + sv.z * qb.z + sv.w * qb.w;
            nrm[k] = sv.x * sv.x + sv.y * sv.y + sv.z * sv.z + sv.w * sv.w;
        }
        #pragma unroll
        for (int k = 0; k < K_; k++) {
            float dk = dot[k], nk = nrm[k];
            #pragma unroll
            for (int off = 16; off > 0; off >>= 1) {
                dk += __shfl_down_sync(0xffffffffu, dk, off);
                nk += __shfl_down_sync(0xffffffffu, nk, off);
            }
            if (lane == 0) {
                s_red[k * 12 + wid]        = dk;
                s_red[(K_ + k) * 12 + wid] = nk;
            }
        }
    }
    __syncthreads();

    // softmax across 5 lanes of warp 0 (lanes 5..7 padded for the butterflies)
    if (wid == 0 && lane < 8) {
        const bool valid = (lane < K_);
        float t = -1e30f;
        if (valid) {
            float dk = 0.f, nk = 0.f;
            #pragma unroll
            for (int w = 0; w < 12; w++) {
                dk += s_red[lane * 12 + w];
                nk += s_red[(K_ + lane) * 12 + w];
            }
            t = tanhf(-(nk - 2.0f * dk + s_c));
        }
        float m = t;
        #pragma unroll
        for (int off = 4; off > 0; off >>= 1)
            m = fmaxf(m, __shfl_xor_sync(0xffu, m, off, 8));
        float e = valid ? __expf(t - m) : 0.f;
        float Z = e;
        #pragma unroll
        for (int off = 4; off > 0; off >>= 1)
            Z += __shfl_xor_sync(0xffu, Z, off, 8);
        if (valid) {
            float wk = e / Z;
            s_w[lane] = wk;
            out[(size_t)B_ * N_ * D_ + bn * K_ + lane] = wk;   // qgw
        }
    }
    __syncthreads();

    if (tid < D4_) {
        float4 acc = make_float4(0.f, 0.f, 0.f, 0.f);
        #pragma unroll
        for (int k = 0; k < K_; k++) {
            float wk = s_w[k];
            float4 sv = s_sv[k * D4_ + col];
            acc.x += wk * sv.x; acc.y += wk * sv.y;
            acc.z += wk * sv.z; acc.w += wk * sv.w;
        }
        ((float4*)out)[(size_t)bn * D4_ + col] = acc;          // agg
    }
}

extern "C" void kernel_launch(void* const* d_in, const int* in_sizes, int n_in,
                              void* d_out, int out_size) {
    const float4* support = (const float4*)d_in[0];
    const float4* query   = (const float4*)d_in[1];
    float* out = (float*)d_out;

    fused_kernel<<<NBLK_, NT_>>>(query, support, out);
}